// round 3
// baseline (speedup 1.0000x reference)
#include <cuda_runtime.h>

// Problem constants (fixed by setup_inputs): frames=64, height=23, width=24,
// hidden=1152, interval=1.
constexpr int FRAMES  = 64;
constexpr int H       = 23;
constexpr int W       = 24;
constexpr int HIDDEN  = 1152;
constexpr int TPF     = H * W;          // 552 tokens per frame
constexpr int TOTAL   = FRAMES * TPF;   // 35328
constexpr int VEC4    = HIDDEN / 4;     // 288 float4 per vector
constexpr int PER_LANE = VEC4 / 32;     // 9 float4 per lane
constexpr float EPS   = 1e-8f;

// One warp per token. Chunked loads: 3 float4 per vector per chunk, 9 LDG.128
// in flight before any FMA consumer. Neighbor pointers are clamped to a safe
// in-bounds vector when the neighbor is invalid (result discarded -> -1), so
// the inner loop is completely branch-free.
__global__ void __launch_bounds__(256, 2)
simdiff_kernel(const float* __restrict__ x,
               float* __restrict__ out_right,
               float* __restrict__ out_down) {
    const int gwarp = (blockIdx.x * blockDim.x + threadIdx.x) >> 5;
    const int lane  = threadIdx.x & 31;
    if (gwarp >= TOTAL) return;

    const int t = gwarp;
    const int f = t / TPF;
    const int i = t - f * TPF;

    const bool frame_valid = (f < FRAMES - 1);        // interval = 1
    const bool r_valid = frame_valid && (i < TPF - 1);
    const bool d_valid = frame_valid && (i < TPF - W);

    if (!frame_valid) {
        if (lane == 0) { out_right[t] = -1.0f; out_down[t] = -1.0f; }
        return;
    }

    // Clamp invalid neighbors to the token itself (in-bounds, L1-hot).
    const int tr = r_valid ? (t + TPF + 1) : t;
    const int td = d_valid ? (t + TPF + W) : t;

    const float4* __restrict__ a  = (const float4*)(x + (size_t)t  * HIDDEN);
    const float4* __restrict__ br = (const float4*)(x + (size_t)tr * HIDDEN);
    const float4* __restrict__ bd = (const float4*)(x + (size_t)td * HIDDEN);

    float na = 0.f, nbr = 0.f, nbd = 0.f, dr = 0.f, dd = 0.f;

#pragma unroll
    for (int c = 0; c < 3; c++) {
        float4 A[3], R[3], D[3];
        // Issue all 9 loads back-to-back (no consumers in between).
#pragma unroll
        for (int j = 0; j < 3; j++) {
            const int idx = lane + 32 * (c * 3 + j);
            A[j] = a[idx];
            R[j] = br[idx];
            D[j] = bd[idx];
        }
#pragma unroll
        for (int j = 0; j < 3; j++) {
            na  = fmaf(A[j].x, A[j].x, na);
            na  = fmaf(A[j].y, A[j].y, na);
            na  = fmaf(A[j].z, A[j].z, na);
            na  = fmaf(A[j].w, A[j].w, na);
            dr  = fmaf(A[j].x, R[j].x, dr);
            dr  = fmaf(A[j].y, R[j].y, dr);
            dr  = fmaf(A[j].z, R[j].z, dr);
            dr  = fmaf(A[j].w, R[j].w, dr);
            nbr = fmaf(R[j].x, R[j].x, nbr);
            nbr = fmaf(R[j].y, R[j].y, nbr);
            nbr = fmaf(R[j].z, R[j].z, nbr);
            nbr = fmaf(R[j].w, R[j].w, nbr);
            dd  = fmaf(A[j].x, D[j].x, dd);
            dd  = fmaf(A[j].y, D[j].y, dd);
            dd  = fmaf(A[j].z, D[j].z, dd);
            dd  = fmaf(A[j].w, D[j].w, dd);
            nbd = fmaf(D[j].x, D[j].x, nbd);
            nbd = fmaf(D[j].y, D[j].y, nbd);
            nbd = fmaf(D[j].z, D[j].z, nbd);
            nbd = fmaf(D[j].w, D[j].w, nbd);
        }
    }

    // warp reduction of the 5 partial sums
#pragma unroll
    for (int off = 16; off > 0; off >>= 1) {
        na  += __shfl_xor_sync(0xFFFFFFFFu, na,  off);
        nbr += __shfl_xor_sync(0xFFFFFFFFu, nbr, off);
        nbd += __shfl_xor_sync(0xFFFFFFFFu, nbd, off);
        dr  += __shfl_xor_sync(0xFFFFFFFFu, dr,  off);
        dd  += __shfl_xor_sync(0xFFFFFFFFu, dd,  off);
    }

    if (lane == 0) {
        float norm_a = fmaxf(sqrtf(na), EPS);
        float rv = -1.0f, dv = -1.0f;
        if (r_valid) rv = dr / (norm_a * fmaxf(sqrtf(nbr), EPS));
        if (d_valid) dv = dd / (norm_a * fmaxf(sqrtf(nbd), EPS));
        out_right[t] = rv;
        out_down[t]  = dv;
    }
}

extern "C" void kernel_launch(void* const* d_in, const int* in_sizes, int n_in,
                              void* d_out, int out_size) {
    const float* x = (const float*)d_in[0];
    float* out = (float*)d_out;
    float* out_right = out;
    float* out_down  = out + TOTAL;

    const int warps_per_block = 256 / 32;                // 8
    const int blocks = (TOTAL + warps_per_block - 1) / warps_per_block;  // 4416
    simdiff_kernel<<<blocks, 256>>>(x, out_right, out_down);
}

// round 7
// speedup vs baseline: 1.6757x; 1.6757x over previous
#include <cuda_runtime.h>

// Problem constants (fixed by setup_inputs): frames=64, height=23, width=24,
// hidden=1152, interval=1.
constexpr int FRAMES  = 64;
constexpr int H       = 23;
constexpr int W       = 24;
constexpr int HIDDEN  = 1152;
constexpr int TPF     = H * W;          // 552 tokens per frame
constexpr int TOTAL   = FRAMES * TPF;   // 35328
constexpr int VEC4    = HIDDEN / 4;     // 288 float4 per vector
constexpr int PER_LANE = VEC4 / 32;     // 9 float4 per lane
constexpr float EPS   = 1e-8f;

// One warp per token. Branch-free (clamped neighbor pointers), depth-2
// software pipeline with 3 loads (A/R/D) per stage: only 24 live load
// registers, so occupancy stays high while keeping 3-6 LDG.128 in flight.
__global__ void __launch_bounds__(256, 4)
simdiff_kernel(const float* __restrict__ x,
               float* __restrict__ out_right,
               float* __restrict__ out_down) {
    const int gwarp = (blockIdx.x * blockDim.x + threadIdx.x) >> 5;
    const int lane  = threadIdx.x & 31;
    if (gwarp >= TOTAL) return;

    const int t = gwarp;
    const int f = t / TPF;
    const int i = t - f * TPF;

    const bool frame_valid = (f < FRAMES - 1);        // interval = 1
    const bool r_valid = frame_valid && (i < TPF - 1);
    const bool d_valid = frame_valid && (i < TPF - W);

    if (!frame_valid) {
        if (lane == 0) { out_right[t] = -1.0f; out_down[t] = -1.0f; }
        return;
    }

    // Clamp invalid neighbors to the token itself (in-bounds; result discarded).
    const int tr = r_valid ? (t + TPF + 1) : t;
    const int td = d_valid ? (t + TPF + W) : t;

    const float4* __restrict__ a  = (const float4*)(x + (size_t)t  * HIDDEN);
    const float4* __restrict__ br = (const float4*)(x + (size_t)tr * HIDDEN);
    const float4* __restrict__ bd = (const float4*)(x + (size_t)td * HIDDEN);

    float na = 0.f, nbr = 0.f, nbd = 0.f, dr = 0.f, dd = 0.f;

    // Depth-2 pipeline: preload stage j while computing stage j-1.
    float4 cA = a[lane], cR = br[lane], cD = bd[lane];

#pragma unroll
    for (int j = 1; j <= PER_LANE; j++) {
        float4 nA, nR, nD;
        if (j < PER_LANE) {
            const int idx = lane + 32 * j;
            nA = a[idx];
            nR = br[idx];
            nD = bd[idx];
        }
        na  = fmaf(cA.x, cA.x, na);
        na  = fmaf(cA.y, cA.y, na);
        na  = fmaf(cA.z, cA.z, na);
        na  = fmaf(cA.w, cA.w, na);
        dr  = fmaf(cA.x, cR.x, dr);
        dr  = fmaf(cA.y, cR.y, dr);
        dr  = fmaf(cA.z, cR.z, dr);
        dr  = fmaf(cA.w, cR.w, dr);
        nbr = fmaf(cR.x, cR.x, nbr);
        nbr = fmaf(cR.y, cR.y, nbr);
        nbr = fmaf(cR.z, cR.z, nbr);
        nbr = fmaf(cR.w, cR.w, nbr);
        dd  = fmaf(cA.x, cD.x, dd);
        dd  = fmaf(cA.y, cD.y, dd);
        dd  = fmaf(cA.z, cD.z, dd);
        dd  = fmaf(cA.w, cD.w, dd);
        nbd = fmaf(cD.x, cD.x, nbd);
        nbd = fmaf(cD.y, cD.y, nbd);
        nbd = fmaf(cD.z, cD.z, nbd);
        nbd = fmaf(cD.w, cD.w, nbd);
        if (j < PER_LANE) { cA = nA; cR = nR; cD = nD; }
    }

    // warp reduction of the 5 partial sums
#pragma unroll
    for (int off = 16; off > 0; off >>= 1) {
        na  += __shfl_xor_sync(0xFFFFFFFFu, na,  off);
        nbr += __shfl_xor_sync(0xFFFFFFFFu, nbr, off);
        nbd += __shfl_xor_sync(0xFFFFFFFFu, nbd, off);
        dr  += __shfl_xor_sync(0xFFFFFFFFu, dr,  off);
        dd  += __shfl_xor_sync(0xFFFFFFFFu, dd,  off);
    }

    if (lane == 0) {
        float norm_a = fmaxf(sqrtf(na), EPS);
        float rv = -1.0f, dv = -1.0f;
        if (r_valid) rv = dr / (norm_a * fmaxf(sqrtf(nbr), EPS));
        if (d_valid) dv = dd / (norm_a * fmaxf(sqrtf(nbd), EPS));
        out_right[t] = rv;
        out_down[t]  = dv;
    }
}

extern "C" void kernel_launch(void* const* d_in, const int* in_sizes, int n_in,
                              void* d_out, int out_size) {
    const float* x = (const float*)d_in[0];
    float* out = (float*)d_out;
    float* out_right = out;
    float* out_down  = out + TOTAL;

    const int warps_per_block = 256 / 32;                // 8
    const int blocks = (TOTAL + warps_per_block - 1) / warps_per_block;  // 4416
    simdiff_kernel<<<blocks, 256>>>(x, out_right, out_down);
}